// round 4
// baseline (speedup 1.0000x reference)
#include <cuda_runtime.h>
#include <cuda_bf16.h>
#include <cstdint>
#include <math.h>

#define DI __device__ __forceinline__

constexpr int TOK = 32768;           // 8 * 64 * 64
constexpr float EPS = 1e-5f;

// ---------------------------------------------------------------------------
// Device scratch
// ---------------------------------------------------------------------------
__device__ __align__(16) __nv_bfloat16 g_xt_hi[TOK * 128], g_xt_lo[TOK * 128];
__device__ __align__(16) __nv_bfloat16 g_a2_hi[TOK * 128], g_a2_lo[TOK * 128];
__device__ __align__(16) float         g_vpom[TOK * 192];
__device__ __align__(16) __nv_bfloat16 g_dcn_hi[TOK * 128], g_dcn_lo[TOK * 128];
__device__ __align__(16) float         g_op[TOK * 128];
__device__ __align__(16) __nv_bfloat16 g_ot_hi[TOK * 128], g_ot_lo[TOK * 128];

__device__ __align__(16) __nv_bfloat16 g_w1h[128 * 128], g_w1l[128 * 128];
__device__ __align__(16) __nv_bfloat16 g_w2h[192 * 128], g_w2l[192 * 128];
__device__ __align__(16) __nv_bfloat16 g_w4h[128 * 128], g_w4l[128 * 128];
__device__ __align__(16) __nv_bfloat16 g_w5h[128 * 128], g_w5l[128 * 128];
__device__ float g_bias0[128], g_bias1[128], g_bcat[192], g_zero[192];

// ---------------------------------------------------------------------------
// Helpers
// ---------------------------------------------------------------------------
DI uint32_t smem_u32(const void* p) {
    uint32_t a;
    asm("{ .reg .u64 t; cvta.to.shared.u64 t, %1; cvt.u32.u64 %0, t; }" : "=r"(a) : "l"(p));
    return a;
}

DI void ldsm4(uint32_t (&r)[4], uint32_t addr) {
    asm volatile("ldmatrix.sync.aligned.m8n8.x4.shared.b16 {%0,%1,%2,%3}, [%4];"
                 : "=r"(r[0]), "=r"(r[1]), "=r"(r[2]), "=r"(r[3]) : "r"(addr));
}

DI void mma16816(float (&d)[4], const uint32_t (&a)[4], uint32_t b0, uint32_t b1) {
    asm volatile("mma.sync.aligned.m16n8k16.row.col.f32.bf16.bf16.f32 "
                 "{%0,%1,%2,%3}, {%4,%5,%6,%7}, {%8,%9}, {%0,%1,%2,%3};"
                 : "+f"(d[0]), "+f"(d[1]), "+f"(d[2]), "+f"(d[3])
                 : "r"(a[0]), "r"(a[1]), "r"(a[2]), "r"(a[3]), "r"(b0), "r"(b1));
}

// XOR-swizzled tile: row stride 256 B (128 bf16), 16B chunk c -> c ^ (row&7)
DI uint32_t tile_off(int r, int chunk) { return (uint32_t)(r * 256 + ((chunk ^ (r & 7)) << 4)); }

DI void load_tile(char* dst, const uint4* __restrict__ src, int R, int t) {
    for (int i = t; i < R * 16; i += 256) {
        int r = i >> 4, c = i & 15;
        *(uint4*)(dst + tile_off(r, c)) = src[i];
    }
}

DI uint32_t pk(float a, float b) {
    __nv_bfloat16 ha = __float2bfloat16(a), hb = __float2bfloat16(b);
    return ((uint32_t)__bfloat16_as_ushort(hb) << 16) | (uint32_t)__bfloat16_as_ushort(ha);
}
DI uint32_t pksplit(float a, float b, float& ra, float& rb) {
    __nv_bfloat16 ha = __float2bfloat16(a), hb = __float2bfloat16(b);
    ra = a - __bfloat162float(ha);
    rb = b - __bfloat162float(hb);
    return ((uint32_t)__bfloat16_as_ushort(hb) << 16) | (uint32_t)__bfloat16_as_ushort(ha);
}

// ---------------------------------------------------------------------------
// Weight prep: fold BN, transpose to [n][k], split bf16 hi/lo
// ---------------------------------------------------------------------------
__global__ void prep_weights(const float* __restrict__ w_pw0, const float* __restrict__ w_pw1,
                             const float* __restrict__ w_vp,  const float* __restrict__ w_om,
                             const float* __restrict__ w_op,
                             const float* __restrict__ bn1_g, const float* __restrict__ bn1_v,
                             const float* __restrict__ bn2_g, const float* __restrict__ bn2_v)
{
    int idx = blockIdx.x * blockDim.x + threadIdx.x;
    if (idx >= 73728) return;
    float w; __nv_bfloat16 *H, *L; int off;
    if (idx < 16384) {                       // pw0 with BN1 folded: [o][c]
        int k = idx & 127;
        w = w_pw0[idx] * bn1_g[k] * rsqrtf(bn1_v[k] + EPS);
        H = g_w1h; L = g_w1l; off = idx;
    } else if (idx < 32768) {                // pw1 with BN2 folded: [o][c]
        int j = idx - 16384; int k = j & 127;
        w = w_pw1[j] * bn2_g[k] * rsqrtf(bn2_v[k] + EPS);
        H = g_w5h; L = g_w5l; off = j;
    } else if (idx < 49152) {                // w_op transposed: B[n][k] = w_op[k][n]
        int j = idx - 32768; int n = j >> 7, k = j & 127;
        w = w_op[k * 128 + n];
        H = g_w4h; L = g_w4l; off = j;
    } else {                                 // [w_vp | w_om] transposed, padded to 192
        int j = idx - 49152; int n = j >> 7, k = j & 127;
        w = (n < 128) ? w_vp[k * 128 + n] : ((n < 155) ? w_om[k * 32 + (n - 128)] : 0.f);
        H = g_w2h; L = g_w2l; off = j;
    }
    __nv_bfloat16 h = __float2bfloat16(w);
    H[off] = h;
    L[off] = __float2bfloat16(w - __bfloat162float(h));
}

__global__ void prep_bias(const float* __restrict__ bn1_g, const float* __restrict__ bn1_b,
                          const float* __restrict__ bn1_m, const float* __restrict__ bn1_v,
                          const float* __restrict__ bn2_g, const float* __restrict__ bn2_b,
                          const float* __restrict__ bn2_m, const float* __restrict__ bn2_v,
                          const float* __restrict__ w_pw0, const float* __restrict__ w_pw1,
                          const float* __restrict__ b_vp,  const float* __restrict__ b_om)
{
    int t = threadIdx.x;
    if (t < 128) {
        float s = 0.f;
        for (int c = 0; c < 128; ++c) {
            float sc = bn1_g[c] * rsqrtf(bn1_v[c] + EPS);
            s += w_pw0[t * 128 + c] * (bn1_b[c] - bn1_m[c] * sc);
        }
        g_bias0[t] = s;
        float s2 = 0.f;
        for (int c = 0; c < 128; ++c) {
            float sc = bn2_g[c] * rsqrtf(bn2_v[c] + EPS);
            s2 += w_pw1[t * 128 + c] * (bn2_b[c] - bn2_m[c] * sc);
        }
        g_bias1[t] = s2;
    }
    if (t < 192) {
        g_bcat[t] = (t < 128) ? b_vp[t] : ((t < 155) ? b_om[t - 128] : 0.f);
        g_zero[t] = 0.f;
    }
}

// ---------------------------------------------------------------------------
// Transpose-convert: per batch view [128 k][4096 s] -> token-major bf16 hi/lo
// ---------------------------------------------------------------------------
__global__ void __launch_bounds__(256, 4)
tconv(const float* __restrict__ in, __nv_bfloat16* __restrict__ oh, __nv_bfloat16* __restrict__ ol)
{
    __shared__ float tile[32][129];
    int b = blockIdx.z, k0 = blockIdx.y * 32, s0 = blockIdx.x * 128;
    const float* src = in + (size_t)b * 524288 + (size_t)k0 * 4096 + s0;
    for (int i = threadIdx.x; i < 1024; i += 256) {
        int kk = i >> 5, s4 = (i & 31) << 2;
        float4 v = *(const float4*)(src + (size_t)kk * 4096 + s4);
        tile[kk][s4] = v.x; tile[kk][s4 + 1] = v.y; tile[kk][s4 + 2] = v.z; tile[kk][s4 + 3] = v.w;
    }
    __syncthreads();
    for (int i = threadIdx.x; i < 1024; i += 256) {
        int s = i >> 3, q = i & 7, k = q << 2;
        float v0 = tile[k][s], v1 = tile[k + 1][s], v2 = tile[k + 2][s], v3 = tile[k + 3][s];
        uint2 hq, lq; float l0, l1, l2, l3;
        hq.x = pksplit(v0, v1, l0, l1); hq.y = pksplit(v2, v3, l2, l3);
        lq.x = pk(l0, l1);              lq.y = pk(l2, l3);
        size_t row = (size_t)b * 4096 + s0 + s;
        ((uint2*)(oh + row * 128 + k0))[q] = hq;
        ((uint2*)(ol + row * 128 + k0))[q] = lq;
    }
}

// ---------------------------------------------------------------------------
// HMMA GEMM: D[m(128 tok)][n<N] = sum_k A[m][k]*W[n][k], bf16x3 split, fp32 acc
// 8 warps as 4(m) x 2(n); warp tile 32 x N/2. K=128 resident in smem.
// modes: 0 fp32 row-major (ldo) | 1 bf16 hi/lo scatter into step-2 A layout
//        2 fp32 NCHW final output
// ---------------------------------------------------------------------------
template<int N>
__global__ void __launch_bounds__(256, 1)
gemm_mma(const __nv_bfloat16* __restrict__ Ah, const __nv_bfloat16* __restrict__ Al,
         const __nv_bfloat16* __restrict__ Bh, const __nv_bfloat16* __restrict__ Bl,
         const float* __restrict__ biasj, int mode,
         float* __restrict__ outF, int ldo,
         __nv_bfloat16* __restrict__ outH, __nv_bfloat16* __restrict__ outL)
{
    constexpr int NW = N / 2;       // per-warp n width
    constexpr int NT = NW / 8;      // n-tiles per warp
    constexpr int NP = NW / 16;     // ldmatrix n-pairs per warp
    extern __shared__ char sm[];
    char* sAh = sm;
    char* sAl = sm + 32768;
    char* sBh = sm + 65536;
    char* sBl = sm + 65536 + N * 256;

    const int t = threadIdx.x, w = t >> 5, l = t & 31;
    const size_t m0 = (size_t)blockIdx.x * 128;

    load_tile(sAh, (const uint4*)(Ah + m0 * 128), 128, t);
    load_tile(sAl, (const uint4*)(Al + m0 * 128), 128, t);
    load_tile(sBh, (const uint4*)Bh, N, t);
    load_tile(sBl, (const uint4*)Bl, N, t);
    __syncthreads();

    const int wm = w & 3, wn = w >> 2;
    const int mr = wm * 32, nb0 = wn * NW;
    const uint32_t uAh = smem_u32(sAh), uAl = smem_u32(sAl);
    const uint32_t uBh = smem_u32(sBh), uBl = smem_u32(sBl);

    float d[2][NT][4];
#pragma unroll
    for (int mt = 0; mt < 2; mt++)
#pragma unroll
        for (int nt = 0; nt < NT; nt++)
#pragma unroll
            for (int i = 0; i < 4; i++) d[mt][nt][i] = 0.f;

    const int arow0   = mr + (l & 15);
    const int akhalf  = l >> 4;             // chunk offset 0/1
    const int brow_off = (l & 7) + ((l & 16) >> 1);
    const int bkhalf  = (l >> 3) & 1;

#pragma unroll
    for (int ks = 0; ks < 8; ks++) {
        uint32_t ah[2][4], al[2][4];
#pragma unroll
        for (int mt = 0; mt < 2; mt++) {
            uint32_t off = tile_off(arow0 + mt * 16, 2 * ks + akhalf);
            ldsm4(ah[mt], uAh + off);
            ldsm4(al[mt], uAl + off);
        }
#pragma unroll
        for (int np = 0; np < NP; np++) {
            uint32_t off = tile_off(nb0 + np * 16 + brow_off, 2 * ks + bkhalf);
            uint32_t bh[4], bl[4];
            ldsm4(bh, uBh + off);
            ldsm4(bl, uBl + off);
#pragma unroll
            for (int mt = 0; mt < 2; mt++) {
                mma16816(d[mt][2 * np],     ah[mt], bh[0], bh[1]);
                mma16816(d[mt][2 * np + 1], ah[mt], bh[2], bh[3]);
                mma16816(d[mt][2 * np],     ah[mt], bl[0], bl[1]);
                mma16816(d[mt][2 * np + 1], ah[mt], bl[2], bl[3]);
                mma16816(d[mt][2 * np],     al[mt], bh[0], bh[1]);
                mma16816(d[mt][2 * np + 1], al[mt], bh[2], bh[3]);
            }
        }
    }
    __syncthreads();   // finished reading A/B tiles; smem reused as stage

    // Stage D (+bias) in smem: float [128][N+1]
    float* stage = (float*)sm;
    constexpr int ldp = N + 1;
    const int rbase = mr + (l >> 2);
    const int cbase = (l & 3) * 2;
#pragma unroll
    for (int mt = 0; mt < 2; mt++) {
#pragma unroll
        for (int nt = 0; nt < NT; nt++) {
            int row = rbase + mt * 16;
            int col = nb0 + nt * 8 + cbase;
            float b0 = biasj[col], b1 = biasj[col + 1];
            stage[row * ldp + col]           = d[mt][nt][0] + b0;
            stage[row * ldp + col + 1]       = d[mt][nt][1] + b1;
            stage[(row + 8) * ldp + col]     = d[mt][nt][2] + b0;
            stage[(row + 8) * ldp + col + 1] = d[mt][nt][3] + b1;
        }
    }
    __syncthreads();

    if (mode == 0) {
        constexpr int q4 = N >> 2;
        for (int i = t; i < 128 * q4; i += 256) {
            int m = i / q4, q = i - m * q4;
            float4 v = make_float4(stage[m * ldp + q * 4],     stage[m * ldp + q * 4 + 1],
                                   stage[m * ldp + q * 4 + 2], stage[m * ldp + q * 4 + 3]);
            *(float4*)(outF + (m0 + m) * (size_t)ldo + q * 4) = v;
        }
    } else if (mode == 1) {
        // raw-reshape scatter: D[(b,s)][n] -> A2[b*4096 + n*32 + s>>7][s&127]
        const int b  = (int)(m0 >> 12);
        const int ss = ((int)m0 & 4095) >> 7;
        for (int i = t; i < 4096; i += 256) {
            int n = i >> 5, q = i & 31;
            float v0 = stage[(q * 4 + 0) * ldp + n], v1 = stage[(q * 4 + 1) * ldp + n];
            float v2 = stage[(q * 4 + 2) * ldp + n], v3 = stage[(q * 4 + 3) * ldp + n];
            uint2 hq, lq; float l0, l1, l2, l3;
            hq.x = pksplit(v0, v1, l0, l1); hq.y = pksplit(v2, v3, l2, l3);
            lq.x = pk(l0, l1);              lq.y = pk(l2, l3);
            size_t row = (size_t)b * 4096 + (size_t)n * 32 + ss;
            ((uint2*)(outH + row * 128))[q] = hq;
            ((uint2*)(outL + row * 128))[q] = lq;
        }
    } else {
        // NCHW store: D[(b, s0+m)][n] -> out[b][n][s0+m]
        const int b  = (int)(m0 >> 12);
        const int s0 = (int)m0 & 4095;
        for (int i = t; i < 4096; i += 256) {
            int n = i >> 5, q = i & 31;
            float4 v = make_float4(stage[(q * 4 + 0) * ldp + n], stage[(q * 4 + 1) * ldp + n],
                                   stage[(q * 4 + 2) * ldp + n], stage[(q * 4 + 3) * ldp + n]);
            *(float4*)(outF + (size_t)b * 524288 + (size_t)n * 4096 + s0 + q * 4) = v;
        }
    }
}

// ---------------------------------------------------------------------------
// DCNv4 core (fp32) -> bf16 hi/lo output
// ---------------------------------------------------------------------------
__global__ void dcn_kernel(const float* __restrict__ vpom,
                           __nv_bfloat16* __restrict__ oh, __nv_bfloat16* __restrict__ ol)
{
    const int warp = threadIdx.x >> 5;
    const int lane = threadIdx.x & 31;
    const int pos  = blockIdx.x * 8 + warp;
    const int b = pos >> 12;
    const int s = pos & 4095;
    const int h = s >> 6;
    const int w = s & 63;

    const float* omp = vpom + (size_t)pos * 192 + 128;
    float omv = (lane < 27) ? omp[lane] : 0.f;

    const float* vb = vpom + ((size_t)b << 12) * 192;
    const int coff = lane << 2;

    float4 acc = make_float4(0.f, 0.f, 0.f, 0.f);

#pragma unroll
    for (int k = 0; k < 9; ++k) {
        float dx = __shfl_sync(0xffffffffu, omv, 3 * k);
        float dy = __shfl_sync(0xffffffffu, omv, 3 * k + 1);
        float m  = __shfl_sync(0xffffffffu, omv, 3 * k + 2);
        float px = (float)(w + (k % 3) - 1) + dx;
        float py = (float)(h + (k / 3) - 1) + dy;
        float xf = floorf(px), yf = floorf(py);
        float fx = px - xf,    fy = py - yf;
        int x0 = (int)xf, y0 = (int)yf;
#pragma unroll
        for (int cy = 0; cy < 2; ++cy) {
#pragma unroll
            for (int cx = 0; cx < 2; ++cx) {
                int xi = x0 + cx, yi = y0 + cy;
                float wt = (cx ? fx : 1.f - fx) * (cy ? fy : 1.f - fy) * m;
                if (xi < 0 || xi > 63 || yi < 0 || yi > 63) wt = 0.f;
                int xc = min(max(xi, 0), 63);
                int yc = min(max(yi, 0), 63);
                const float4 v = *(const float4*)(vb + (size_t)(yc * 64 + xc) * 192 + coff);
                acc.x += wt * v.x; acc.y += wt * v.y;
                acc.z += wt * v.z; acc.w += wt * v.w;
            }
        }
    }
    uint2 hq, lq; float l0, l1, l2, l3;
    hq.x = pksplit(acc.x, acc.y, l0, l1); hq.y = pksplit(acc.z, acc.w, l2, l3);
    lq.x = pk(l0, l1);                    lq.y = pk(l2, l3);
    *(uint2*)(oh + (size_t)pos * 128 + coff) = hq;
    *(uint2*)(ol + (size_t)pos * 128 + coff) = lq;
}

// ---------------------------------------------------------------------------
// Launcher
// ---------------------------------------------------------------------------
extern "C" void kernel_launch(void* const* d_in, const int* in_sizes, int n_in,
                              void* d_out, int out_size)
{
    (void)in_sizes; (void)n_in; (void)out_size;
    const float* x     = (const float*)d_in[0];
    const float* bn1_g = (const float*)d_in[1];
    const float* bn1_b = (const float*)d_in[2];
    const float* bn1_m = (const float*)d_in[3];
    const float* bn1_v = (const float*)d_in[4];
    const float* w_pw0 = (const float*)d_in[5];
    const float* w_vp  = (const float*)d_in[6];
    const float* b_vp  = (const float*)d_in[7];
    const float* w_om  = (const float*)d_in[8];
    const float* b_om  = (const float*)d_in[9];
    const float* w_op  = (const float*)d_in[10];
    const float* bn2_g = (const float*)d_in[11];
    const float* bn2_b = (const float*)d_in[12];
    const float* bn2_m = (const float*)d_in[13];
    const float* bn2_v = (const float*)d_in[14];
    const float* w_pw1 = (const float*)d_in[15];
    float* out = (float*)d_out;

    __nv_bfloat16 *xth, *xtl, *a2h, *a2l, *dch, *dcl, *oth, *otl;
    __nv_bfloat16 *w1h, *w1l, *w2h, *w2l, *w4h, *w4l, *w5h, *w5l;
    float *vpom, *op, *bias0, *bias1, *bcat, *zero;
    cudaGetSymbolAddress((void**)&xth, g_xt_hi);  cudaGetSymbolAddress((void**)&xtl, g_xt_lo);
    cudaGetSymbolAddress((void**)&a2h, g_a2_hi);  cudaGetSymbolAddress((void**)&a2l, g_a2_lo);
    cudaGetSymbolAddress((void**)&dch, g_dcn_hi); cudaGetSymbolAddress((void**)&dcl, g_dcn_lo);
    cudaGetSymbolAddress((void**)&oth, g_ot_hi);  cudaGetSymbolAddress((void**)&otl, g_ot_lo);
    cudaGetSymbolAddress((void**)&w1h, g_w1h);    cudaGetSymbolAddress((void**)&w1l, g_w1l);
    cudaGetSymbolAddress((void**)&w2h, g_w2h);    cudaGetSymbolAddress((void**)&w2l, g_w2l);
    cudaGetSymbolAddress((void**)&w4h, g_w4h);    cudaGetSymbolAddress((void**)&w4l, g_w4l);
    cudaGetSymbolAddress((void**)&w5h, g_w5h);    cudaGetSymbolAddress((void**)&w5l, g_w5l);
    cudaGetSymbolAddress((void**)&vpom, g_vpom);  cudaGetSymbolAddress((void**)&op, g_op);
    cudaGetSymbolAddress((void**)&bias0, g_bias0); cudaGetSymbolAddress((void**)&bias1, g_bias1);
    cudaGetSymbolAddress((void**)&bcat, g_bcat);  cudaGetSymbolAddress((void**)&zero, g_zero);

    const int SM128 = 65536 + 2 * 128 * 256;   // 131072
    const int SM192 = 65536 + 2 * 192 * 256;   // 163840
    cudaFuncSetAttribute(gemm_mma<128>, cudaFuncAttributeMaxDynamicSharedMemorySize, SM128);
    cudaFuncSetAttribute(gemm_mma<192>, cudaFuncAttributeMaxDynamicSharedMemorySize, SM192);

    prep_weights<<<288, 256>>>(w_pw0, w_pw1, w_vp, w_om, w_op, bn1_g, bn1_v, bn2_g, bn2_v);
    prep_bias<<<1, 256>>>(bn1_g, bn1_b, bn1_m, bn1_v, bn2_g, bn2_b, bn2_m, bn2_v,
                          w_pw0, w_pw1, b_vp, b_om);

    // 1) x (NCHW) -> token-major hi/lo; x1 = x @ w1^T + bias0 scattered into
    //    step-2's raw-reshape A layout.
    tconv<<<dim3(32, 4, 8), 256>>>(x, xth, xtl);
    gemm_mma<128><<<256, 256, SM128>>>(xth, xtl, w1h, w1l, bias0, 1, nullptr, 0, a2h, a2l);

    // 2) vpom = x1_view @ [w_vp|w_om]^T + bcat  (fp32, ld 192)
    gemm_mma<192><<<256, 256, SM192>>>(a2h, a2l, w2h, w2l, bcat, 0, vpom, 192, nullptr, nullptr);

    // 3) DCNv4 core -> bf16 hi/lo
    dcn_kernel<<<4096, 256>>>(vpom, dch, dcl);

    // 4) op = dcn @ w_op  (fp32 token-major = NCHW raw view)
    gemm_mma<128><<<256, 256, SM128>>>(dch, dcl, w4h, w4l, zero, 0, op, 128, nullptr, nullptr);

    // 5) out = (BN2-folded pw1) on NCHW view of op
    tconv<<<dim3(32, 4, 8), 256>>>(op, oth, otl);
    gemm_mma<128><<<256, 256, SM128>>>(oth, otl, w5h, w5l, bias1, 2, out, 0, nullptr, nullptr);
}

// round 5
// speedup vs baseline: 1.4801x; 1.4801x over previous
#include <cuda_runtime.h>
#include <cuda_bf16.h>
#include <cstdint>
#include <math.h>

#define DI __device__ __forceinline__

constexpr int TOK = 32768;           // 8 * 64 * 64
constexpr float EPS = 1e-5f;
constexpr int CHUNKS = TOK / 64;     // 512 chunks of 64 tokens

// ---------------------------------------------------------------------------
// Device scratch
// ---------------------------------------------------------------------------
__device__ __align__(16) __nv_bfloat16 g_xt_hi[TOK * 128], g_xt_lo[TOK * 128];
__device__ __align__(16) __nv_bfloat16 g_a2_hi[TOK * 128], g_a2_lo[TOK * 128];
__device__ __align__(16) float         g_vpom[TOK * 192];
__device__ __align__(16) __nv_bfloat16 g_dcn_hi[TOK * 128], g_dcn_lo[TOK * 128];
__device__ __align__(16) float         g_op[TOK * 128];
__device__ __align__(16) __nv_bfloat16 g_ot_hi[TOK * 128], g_ot_lo[TOK * 128];

__device__ __align__(16) __nv_bfloat16 g_w1h[128 * 128], g_w1l[128 * 128];
__device__ __align__(16) __nv_bfloat16 g_w2h[192 * 128], g_w2l[192 * 128];
__device__ __align__(16) __nv_bfloat16 g_w4h[128 * 128], g_w4l[128 * 128];
__device__ __align__(16) __nv_bfloat16 g_w5h[128 * 128], g_w5l[128 * 128];
__device__ float g_bias0[128], g_bias1[128], g_bcat[192], g_zero[192];

// ---------------------------------------------------------------------------
// Helpers
// ---------------------------------------------------------------------------
DI uint32_t smem_u32(const void* p) {
    uint32_t a;
    asm("{ .reg .u64 t; cvta.to.shared.u64 t, %1; cvt.u32.u64 %0, t; }" : "=r"(a) : "l"(p));
    return a;
}

DI void cpa16(uint32_t dst, const void* src) {
    asm volatile("{ .reg .u64 g; cvta.to.global.u64 g, %1; "
                 "cp.async.cg.shared.global [%0], [g], 16; }"
                 :: "r"(dst), "l"(src));
}
DI void cpa_commit() { asm volatile("cp.async.commit_group;" ::: "memory"); }
DI void cpa_wait0() { asm volatile("cp.async.wait_group 0;" ::: "memory"); }
DI void cpa_wait1() { asm volatile("cp.async.wait_group 1;" ::: "memory"); }

DI void ldsm4(uint32_t (&r)[4], uint32_t addr) {
    asm volatile("ldmatrix.sync.aligned.m8n8.x4.shared.b16 {%0,%1,%2,%3}, [%4];"
                 : "=r"(r[0]), "=r"(r[1]), "=r"(r[2]), "=r"(r[3]) : "r"(addr));
}

DI void mma16816(float (&d)[4], const uint32_t (&a)[4], uint32_t b0, uint32_t b1) {
    asm volatile("mma.sync.aligned.m16n8k16.row.col.f32.bf16.bf16.f32 "
                 "{%0,%1,%2,%3}, {%4,%5,%6,%7}, {%8,%9}, {%0,%1,%2,%3};"
                 : "+f"(d[0]), "+f"(d[1]), "+f"(d[2]), "+f"(d[3])
                 : "r"(a[0]), "r"(a[1]), "r"(a[2]), "r"(a[3]), "r"(b0), "r"(b1));
}

// XOR-swizzled tile: row stride 256 B (128 bf16), 16B chunk c -> c ^ (row&7)
DI uint32_t tile_off(int r, int chunk) { return (uint32_t)(r * 256 + ((chunk ^ (r & 7)) << 4)); }

DI uint32_t pk(float a, float b) {
    __nv_bfloat16 ha = __float2bfloat16(a), hb = __float2bfloat16(b);
    return ((uint32_t)__bfloat16_as_ushort(hb) << 16) | (uint32_t)__bfloat16_as_ushort(ha);
}
DI uint32_t pksplit(float a, float b, float& ra, float& rb) {
    __nv_bfloat16 ha = __float2bfloat16(a), hb = __float2bfloat16(b);
    ra = a - __bfloat162float(ha);
    rb = b - __bfloat162float(hb);
    return ((uint32_t)__bfloat16_as_ushort(hb) << 16) | (uint32_t)__bfloat16_as_ushort(ha);
}

// Async-load one 64-token A chunk (hi at dst, lo at dst+16384), swizzled.
DI void load_chunkA(uint32_t dst, const __nv_bfloat16* __restrict__ Ah,
                    const __nv_bfloat16* __restrict__ Al, size_t m0, int t)
{
    const uint4* sh_ = (const uint4*)(Ah + m0 * 128);
    const uint4* sl_ = (const uint4*)(Al + m0 * 128);
    for (int i = t; i < 1024; i += 256) {
        int r = i >> 4, c = i & 15;
        uint32_t o = tile_off(r, c);
        cpa16(dst + o, sh_ + i);
        cpa16(dst + 16384 + o, sl_ + i);
    }
}

// ---------------------------------------------------------------------------
// Weight prep: fold BN, transpose to [n][k], split bf16 hi/lo
// ---------------------------------------------------------------------------
__global__ void prep_weights(const float* __restrict__ w_pw0, const float* __restrict__ w_pw1,
                             const float* __restrict__ w_vp,  const float* __restrict__ w_om,
                             const float* __restrict__ w_op,
                             const float* __restrict__ bn1_g, const float* __restrict__ bn1_v,
                             const float* __restrict__ bn2_g, const float* __restrict__ bn2_v)
{
    int idx = blockIdx.x * blockDim.x + threadIdx.x;
    if (idx >= 73728) return;
    float w; __nv_bfloat16 *H, *L; int off;
    if (idx < 16384) {
        int k = idx & 127;
        w = w_pw0[idx] * bn1_g[k] * rsqrtf(bn1_v[k] + EPS);
        H = g_w1h; L = g_w1l; off = idx;
    } else if (idx < 32768) {
        int j = idx - 16384; int k = j & 127;
        w = w_pw1[j] * bn2_g[k] * rsqrtf(bn2_v[k] + EPS);
        H = g_w5h; L = g_w5l; off = j;
    } else if (idx < 49152) {
        int j = idx - 32768; int n = j >> 7, k = j & 127;
        w = w_op[k * 128 + n];
        H = g_w4h; L = g_w4l; off = j;
    } else {
        int j = idx - 49152; int n = j >> 7, k = j & 127;
        w = (n < 128) ? w_vp[k * 128 + n] : ((n < 155) ? w_om[k * 32 + (n - 128)] : 0.f);
        H = g_w2h; L = g_w2l; off = j;
    }
    __nv_bfloat16 h = __float2bfloat16(w);
    H[off] = h;
    L[off] = __float2bfloat16(w - __bfloat162float(h));
}

__global__ void prep_bias(const float* __restrict__ bn1_g, const float* __restrict__ bn1_b,
                          const float* __restrict__ bn1_m, const float* __restrict__ bn1_v,
                          const float* __restrict__ bn2_g, const float* __restrict__ bn2_b,
                          const float* __restrict__ bn2_m, const float* __restrict__ bn2_v,
                          const float* __restrict__ w_pw0, const float* __restrict__ w_pw1,
                          const float* __restrict__ b_vp,  const float* __restrict__ b_om)
{
    int t = threadIdx.x;
    if (t < 128) {
        float s = 0.f;
        for (int c = 0; c < 128; ++c) {
            float sc = bn1_g[c] * rsqrtf(bn1_v[c] + EPS);
            s += w_pw0[t * 128 + c] * (bn1_b[c] - bn1_m[c] * sc);
        }
        g_bias0[t] = s;
        float s2 = 0.f;
        for (int c = 0; c < 128; ++c) {
            float sc = bn2_g[c] * rsqrtf(bn2_v[c] + EPS);
            s2 += w_pw1[t * 128 + c] * (bn2_b[c] - bn2_m[c] * sc);
        }
        g_bias1[t] = s2;
    }
    if (t < 192) {
        g_bcat[t] = (t < 128) ? b_vp[t] : ((t < 155) ? b_om[t - 128] : 0.f);
        g_zero[t] = 0.f;
    }
}

// ---------------------------------------------------------------------------
// Transpose-convert: per batch view [128 k][4096 s] -> token-major bf16 hi/lo
// ---------------------------------------------------------------------------
__global__ void __launch_bounds__(256, 4)
tconv(const float* __restrict__ in, __nv_bfloat16* __restrict__ oh, __nv_bfloat16* __restrict__ ol)
{
    __shared__ float tile[32][129];
    int b = blockIdx.z, k0 = blockIdx.y * 32, s0 = blockIdx.x * 128;
    const float* src = in + (size_t)b * 524288 + (size_t)k0 * 4096 + s0;
    for (int i = threadIdx.x; i < 1024; i += 256) {
        int kk = i >> 5, s4 = (i & 31) << 2;
        float4 v = *(const float4*)(src + (size_t)kk * 4096 + s4);
        tile[kk][s4] = v.x; tile[kk][s4 + 1] = v.y; tile[kk][s4 + 2] = v.z; tile[kk][s4 + 3] = v.w;
    }
    __syncthreads();
    for (int i = threadIdx.x; i < 1024; i += 256) {
        int s = i >> 3, q = i & 7, k = q << 2;
        float v0 = tile[k][s], v1 = tile[k + 1][s], v2 = tile[k + 2][s], v3 = tile[k + 3][s];
        uint2 hq, lq; float l0, l1, l2, l3;
        hq.x = pksplit(v0, v1, l0, l1); hq.y = pksplit(v2, v3, l2, l3);
        lq.x = pk(l0, l1);              lq.y = pk(l2, l3);
        size_t row = (size_t)b * 4096 + s0 + s;
        ((uint2*)(oh + row * 128 + k0))[q] = hq;
        ((uint2*)(ol + row * 128 + k0))[q] = lq;
    }
}

// ---------------------------------------------------------------------------
// Persistent chunk-loop HMMA GEMM. bf16x3 split (AhBh+AhBl+AlBh), fp32 acc.
// Grid = #SMs; each CTA loads B once, then loops 64-token chunks with
// cp.async double-buffered A prefetch.
// MODE 0: fp32 row-major direct register stores (ldo)
// MODE 1: bf16 hi/lo raw-reshape scatter into step-2 A layout (smem stage)
// MODE 2: fp32 NCHW final output (smem stage)
// ---------------------------------------------------------------------------
template<int N, int MODE>
__global__ void __launch_bounds__(256, 1)
gemm_mma(const __nv_bfloat16* __restrict__ Ah, const __nv_bfloat16* __restrict__ Al,
         const __nv_bfloat16* __restrict__ Bh, const __nv_bfloat16* __restrict__ Bl,
         const float* __restrict__ biasj,
         float* __restrict__ outF, int ldo,
         __nv_bfloat16* __restrict__ outH, __nv_bfloat16* __restrict__ outL)
{
    constexpr int NW = N / 4;        // per-warp n width (8 warps = 2m x 4n)
    constexpr int NT = NW / 8;       // 8-col n-tiles per warp
    constexpr int NP = NW / 16;      // ldmatrix n-pairs per warp
    constexpr int BOFF = 2 * N * 256;            // B hi+lo bytes
    constexpr int ldp = N + 1;

    extern __shared__ char sm[];
    const uint32_t uSM = smem_u32(sm);
    const uint32_t uBh = uSM, uBl = uSM + N * 256;
    float* stage = (float*)(sm + BOFF + 65536);

    const int t = threadIdx.x, w = t >> 5, l = t & 31;
    const int wm = w & 1, wn = w >> 1;
    const int mr = wm * 32, nb0 = wn * NW;

    // hoist bias for this thread's columns
    const int cbase = (l & 3) * 2;
    float bj0[NT], bj1[NT];
#pragma unroll
    for (int nt = 0; nt < NT; nt++) {
        int col = nb0 + nt * 8 + cbase;
        bj0[nt] = biasj[col];
        bj1[nt] = biasj[col + 1];
    }

    // B load (once)
    {
        const uint4* sh_ = (const uint4*)Bh;
        const uint4* sl_ = (const uint4*)Bl;
        for (int i = t; i < N * 16; i += 256) {
            int r = i >> 4, c = i & 15;
            uint32_t o = tile_off(r, c);
            cpa16(uBh + o, sh_ + i);
            cpa16(uBl + o, sl_ + i);
        }
    }
    int cid = blockIdx.x;
    load_chunkA(uSM + BOFF, Ah, Al, (size_t)cid * 64, t);
    cpa_commit();

    const int arow0 = mr + (l & 15);
    const int akhalf = l >> 4;
    const int brow_off = (l & 7) + ((l & 16) >> 1);
    const int bkhalf = (l >> 3) & 1;

    int p = 0;
    while (cid < CHUNKS) {
        const int nxt = cid + (int)gridDim.x;
        const bool hasnext = nxt < CHUNKS;
        if (hasnext) {
            load_chunkA(uSM + BOFF + (p ^ 1) * 32768, Ah, Al, (size_t)nxt * 64, t);
            cpa_commit();
            cpa_wait1();
        } else {
            cpa_wait0();
        }
        __syncthreads();

        const uint32_t uAh = uSM + BOFF + p * 32768;
        const uint32_t uAl = uAh + 16384;

        float d[2][NT][4];
#pragma unroll
        for (int mt = 0; mt < 2; mt++)
#pragma unroll
            for (int nt = 0; nt < NT; nt++)
#pragma unroll
                for (int i = 0; i < 4; i++) d[mt][nt][i] = 0.f;

#pragma unroll
        for (int ks = 0; ks < 8; ks++) {
            uint32_t ah[2][4], al[2][4];
#pragma unroll
            for (int mt = 0; mt < 2; mt++) {
                uint32_t off = tile_off(arow0 + mt * 16, 2 * ks + akhalf);
                ldsm4(ah[mt], uAh + off);
                ldsm4(al[mt], uAl + off);
            }
#pragma unroll
            for (int np = 0; np < NP; np++) {
                uint32_t off = tile_off(nb0 + np * 16 + brow_off, 2 * ks + bkhalf);
                uint32_t bh[4], bl[4];
                ldsm4(bh, uBh + off);
                ldsm4(bl, uBl + off);
#pragma unroll
                for (int mt = 0; mt < 2; mt++) {
                    mma16816(d[mt][2 * np],     ah[mt], bh[0], bh[1]);
                    mma16816(d[mt][2 * np + 1], ah[mt], bh[2], bh[3]);
                    mma16816(d[mt][2 * np],     ah[mt], bl[0], bl[1]);
                    mma16816(d[mt][2 * np + 1], ah[mt], bl[2], bl[3]);
                    mma16816(d[mt][2 * np],     al[mt], bh[0], bh[1]);
                    mma16816(d[mt][2 * np + 1], al[mt], bh[2], bh[3]);
                }
            }
        }

        const size_t m0 = (size_t)cid * 64;
        const int rbase = mr + (l >> 2);

        if (MODE == 0) {
            // direct register stores, row-major fp32
#pragma unroll
            for (int mt = 0; mt < 2; mt++) {
#pragma unroll
                for (int nt = 0; nt < NT; nt++) {
                    int row = rbase + mt * 16;
                    int col = nb0 + nt * 8 + cbase;
                    float2 v0 = make_float2(d[mt][nt][0] + bj0[nt], d[mt][nt][1] + bj1[nt]);
                    float2 v1 = make_float2(d[mt][nt][2] + bj0[nt], d[mt][nt][3] + bj1[nt]);
                    *(float2*)(outF + (m0 + row) * (size_t)ldo + col) = v0;
                    *(float2*)(outF + (m0 + row + 8) * (size_t)ldo + col) = v1;
                }
            }
        } else {
            // stage (rows = 64 local tokens)
#pragma unroll
            for (int mt = 0; mt < 2; mt++) {
#pragma unroll
                for (int nt = 0; nt < NT; nt++) {
                    int row = rbase + mt * 16;
                    int col = nb0 + nt * 8 + cbase;
                    stage[row * ldp + col]           = d[mt][nt][0] + bj0[nt];
                    stage[row * ldp + col + 1]       = d[mt][nt][1] + bj1[nt];
                    stage[(row + 8) * ldp + col]     = d[mt][nt][2] + bj0[nt];
                    stage[(row + 8) * ldp + col + 1] = d[mt][nt][3] + bj1[nt];
                }
            }
            __syncthreads();
            if (MODE == 1) {
                // scatter: D[(b,s)][n] -> A2[b*4096 + n*32 + s>>7][s&127]
                const int b  = (int)(m0 >> 12);
                const int sh = (int)((m0 & 4095) >> 7);
                const int cb = (int)(m0 & 64);
                for (int i = t; i < N * 16; i += 256) {
                    int n = i >> 4, q = i & 15, j0 = q * 4;
                    float v0 = stage[(j0 + 0) * ldp + n], v1 = stage[(j0 + 1) * ldp + n];
                    float v2 = stage[(j0 + 2) * ldp + n], v3 = stage[(j0 + 3) * ldp + n];
                    uint2 hq, lq; float r0, r1, r2, r3;
                    hq.x = pksplit(v0, v1, r0, r1); hq.y = pksplit(v2, v3, r2, r3);
                    lq.x = pk(r0, r1);              lq.y = pk(r2, r3);
                    size_t row = (size_t)b * 4096 + (size_t)n * 32 + sh;
                    ((uint2*)(outH + row * 128 + cb))[q] = hq;
                    ((uint2*)(outL + row * 128 + cb))[q] = lq;
                }
            } else {
                // NCHW: D[(b, s0+j)][n] -> out[b][n][s0+j]
                const int b  = (int)(m0 >> 12);
                const int s0 = (int)(m0 & 4095);
                for (int i = t; i < N * 16; i += 256) {
                    int n = i >> 4, q = i & 15, j0 = q * 4;
                    float4 v = make_float4(stage[(j0 + 0) * ldp + n], stage[(j0 + 1) * ldp + n],
                                           stage[(j0 + 2) * ldp + n], stage[(j0 + 3) * ldp + n]);
                    *(float4*)(outF + (size_t)b * 524288 + (size_t)n * 4096 + s0 + j0) = v;
                }
            }
        }
        __syncthreads();   // protect A buffer / stage before next iteration
        p ^= 1;
        cid = nxt;
    }
}

// ---------------------------------------------------------------------------
// DCNv4 core (fp32) -> bf16 hi/lo output
// ---------------------------------------------------------------------------
__global__ void dcn_kernel(const float* __restrict__ vpom,
                           __nv_bfloat16* __restrict__ oh, __nv_bfloat16* __restrict__ ol)
{
    const int warp = threadIdx.x >> 5;
    const int lane = threadIdx.x & 31;
    const int pos  = blockIdx.x * 8 + warp;
    const int b = pos >> 12;
    const int s = pos & 4095;
    const int h = s >> 6;
    const int w = s & 63;

    const float* omp = vpom + (size_t)pos * 192 + 128;
    float omv = (lane < 27) ? omp[lane] : 0.f;

    const float* vb = vpom + ((size_t)b << 12) * 192;
    const int coff = lane << 2;

    float4 acc = make_float4(0.f, 0.f, 0.f, 0.f);

#pragma unroll
    for (int k = 0; k < 9; ++k) {
        float dx = __shfl_sync(0xffffffffu, omv, 3 * k);
        float dy = __shfl_sync(0xffffffffu, omv, 3 * k + 1);
        float m  = __shfl_sync(0xffffffffu, omv, 3 * k + 2);
        float px = (float)(w + (k % 3) - 1) + dx;
        float py = (float)(h + (k / 3) - 1) + dy;
        float xf = floorf(px), yf = floorf(py);
        float fx = px - xf,    fy = py - yf;
        int x0 = (int)xf, y0 = (int)yf;
#pragma unroll
        for (int cy = 0; cy < 2; ++cy) {
#pragma unroll
            for (int cx = 0; cx < 2; ++cx) {
                int xi = x0 + cx, yi = y0 + cy;
                float wt = (cx ? fx : 1.f - fx) * (cy ? fy : 1.f - fy) * m;
                if (xi < 0 || xi > 63 || yi < 0 || yi > 63) wt = 0.f;
                int xc = min(max(xi, 0), 63);
                int yc = min(max(yi, 0), 63);
                const float4 v = *(const float4*)(vb + (size_t)(yc * 64 + xc) * 192 + coff);
                acc.x += wt * v.x; acc.y += wt * v.y;
                acc.z += wt * v.z; acc.w += wt * v.w;
            }
        }
    }
    uint2 hq, lq; float l0, l1, l2, l3;
    hq.x = pksplit(acc.x, acc.y, l0, l1); hq.y = pksplit(acc.z, acc.w, l2, l3);
    lq.x = pk(l0, l1);                    lq.y = pk(l2, l3);
    *(uint2*)(oh + (size_t)pos * 128 + coff) = hq;
    *(uint2*)(ol + (size_t)pos * 128 + coff) = lq;
}

// ---------------------------------------------------------------------------
// Launcher
// ---------------------------------------------------------------------------
extern "C" void kernel_launch(void* const* d_in, const int* in_sizes, int n_in,
                              void* d_out, int out_size)
{
    (void)in_sizes; (void)n_in; (void)out_size;
    const float* x     = (const float*)d_in[0];
    const float* bn1_g = (const float*)d_in[1];
    const float* bn1_b = (const float*)d_in[2];
    const float* bn1_m = (const float*)d_in[3];
    const float* bn1_v = (const float*)d_in[4];
    const float* w_pw0 = (const float*)d_in[5];
    const float* w_vp  = (const float*)d_in[6];
    const float* b_vp  = (const float*)d_in[7];
    const float* w_om  = (const float*)d_in[8];
    const float* b_om  = (const float*)d_in[9];
    const float* w_op  = (const float*)d_in[10];
    const float* bn2_g = (const float*)d_in[11];
    const float* bn2_b = (const float*)d_in[12];
    const float* bn2_m = (const float*)d_in[13];
    const float* bn2_v = (const float*)d_in[14];
    const float* w_pw1 = (const float*)d_in[15];
    float* out = (float*)d_out;

    __nv_bfloat16 *xth, *xtl, *a2h, *a2l, *dch, *dcl, *oth, *otl;
    __nv_bfloat16 *w1h, *w1l, *w2h, *w2l, *w4h, *w4l, *w5h, *w5l;
    float *vpom, *op, *bias0, *bias1, *bcat, *zero;
    cudaGetSymbolAddress((void**)&xth, g_xt_hi);  cudaGetSymbolAddress((void**)&xtl, g_xt_lo);
    cudaGetSymbolAddress((void**)&a2h, g_a2_hi);  cudaGetSymbolAddress((void**)&a2l, g_a2_lo);
    cudaGetSymbolAddress((void**)&dch, g_dcn_hi); cudaGetSymbolAddress((void**)&dcl, g_dcn_lo);
    cudaGetSymbolAddress((void**)&oth, g_ot_hi);  cudaGetSymbolAddress((void**)&otl, g_ot_lo);
    cudaGetSymbolAddress((void**)&w1h, g_w1h);    cudaGetSymbolAddress((void**)&w1l, g_w1l);
    cudaGetSymbolAddress((void**)&w2h, g_w2h);    cudaGetSymbolAddress((void**)&w2l, g_w2l);
    cudaGetSymbolAddress((void**)&w4h, g_w4h);    cudaGetSymbolAddress((void**)&w4l, g_w4l);
    cudaGetSymbolAddress((void**)&w5h, g_w5h);    cudaGetSymbolAddress((void**)&w5l, g_w5l);
    cudaGetSymbolAddress((void**)&vpom, g_vpom);  cudaGetSymbolAddress((void**)&op, g_op);
    cudaGetSymbolAddress((void**)&bias0, g_bias0); cudaGetSymbolAddress((void**)&bias1, g_bias1);
    cudaGetSymbolAddress((void**)&bcat, g_bcat);  cudaGetSymbolAddress((void**)&zero, g_zero);

    // smem: B(2*N*256) + A double buffer(65536) + stage(64*(N+1)*4)
    const int SM128 = 2 * 128 * 256 + 65536 + 64 * 129 * 4;   // 164096
    const int SM192 = 2 * 192 * 256 + 65536 + 64 * 193 * 4;   // 213248
    cudaFuncSetAttribute(gemm_mma<128, 0>, cudaFuncAttributeMaxDynamicSharedMemorySize, SM128);
    cudaFuncSetAttribute(gemm_mma<128, 1>, cudaFuncAttributeMaxDynamicSharedMemorySize, SM128);
    cudaFuncSetAttribute(gemm_mma<128, 2>, cudaFuncAttributeMaxDynamicSharedMemorySize, SM128);
    cudaFuncSetAttribute(gemm_mma<192, 0>, cudaFuncAttributeMaxDynamicSharedMemorySize, SM192);

    const int GRID = 148;   // one persistent CTA per SM

    prep_weights<<<288, 256>>>(w_pw0, w_pw1, w_vp, w_om, w_op, bn1_g, bn1_v, bn2_g, bn2_v);
    prep_bias<<<1, 256>>>(bn1_g, bn1_b, bn1_m, bn1_v, bn2_g, bn2_b, bn2_m, bn2_v,
                          w_pw0, w_pw1, b_vp, b_om);

    // 1) x (NCHW) -> token-major hi/lo; x1 = x @ w1^T + bias0 scattered into
    //    step-2's raw-reshape A layout.
    tconv<<<dim3(32, 4, 8), 256>>>(x, xth, xtl);
    gemm_mma<128, 1><<<GRID, 256, SM128>>>(xth, xtl, w1h, w1l, bias0, nullptr, 0, a2h, a2l);

    // 2) vpom = x1_view @ [w_vp|w_om]^T + bcat  (fp32, ld 192)
    gemm_mma<192, 0><<<GRID, 256, SM192>>>(a2h, a2l, w2h, w2l, bcat, vpom, 192, nullptr, nullptr);

    // 3) DCNv4 core -> bf16 hi/lo
    dcn_kernel<<<4096, 256>>>(vpom, dch, dcl);

    // 4) op = dcn @ w_op  (fp32 token-major = NCHW raw view)
    gemm_mma<128, 0><<<GRID, 256, SM128>>>(dch, dcl, w4h, w4l, zero, op, 128, nullptr, nullptr);

    // 5) out = (BN2-folded pw1) on NCHW view of op
    tconv<<<dim3(32, 4, 8), 256>>>(op, oth, otl);
    gemm_mma<128, 2><<<GRID, 256, SM128>>>(oth, otl, w5h, w5l, bias1, out, 0, nullptr, nullptr);
}

// round 6
// speedup vs baseline: 1.5453x; 1.0440x over previous
#include <cuda_runtime.h>
#include <cuda_bf16.h>
#include <cstdint>
#include <math.h>

#define DI __device__ __forceinline__

constexpr int TOK = 32768;           // 8 * 64 * 64
constexpr float EPS = 1e-5f;
constexpr int CH = 32;               // tokens per chunk
constexpr int CHUNKS = TOK / CH;     // 1024

// ---------------------------------------------------------------------------
// Device scratch
// ---------------------------------------------------------------------------
__device__ __align__(16) __nv_bfloat16 g_xt_hi[TOK * 128], g_xt_lo[TOK * 128];
__device__ __align__(16) __nv_bfloat16 g_a2_hi[TOK * 128], g_a2_lo[TOK * 128];
__device__ __align__(16) float         g_vpom[TOK * 192];
__device__ __align__(16) __nv_bfloat16 g_dcn_hi[TOK * 128], g_dcn_lo[TOK * 128];
__device__ __align__(16) float         g_op[TOK * 128];
__device__ __align__(16) __nv_bfloat16 g_ot_hi[TOK * 128], g_ot_lo[TOK * 128];

__device__ __align__(16) __nv_bfloat16 g_w1h[128 * 128], g_w1l[128 * 128];
__device__ __align__(16) __nv_bfloat16 g_w2h[192 * 128], g_w2l[192 * 128];
__device__ __align__(16) __nv_bfloat16 g_w4h[128 * 128], g_w4l[128 * 128];
__device__ __align__(16) __nv_bfloat16 g_w5h[128 * 128], g_w5l[128 * 128];
__device__ float g_bias0[128], g_bias1[128], g_bcat[192], g_zero[192];

// ---------------------------------------------------------------------------
// Helpers
// ---------------------------------------------------------------------------
DI uint32_t smem_u32(const void* p) {
    uint32_t a;
    asm("{ .reg .u64 t; cvta.to.shared.u64 t, %1; cvt.u32.u64 %0, t; }" : "=r"(a) : "l"(p));
    return a;
}

DI void cpa16(uint32_t dst, const void* src) {
    asm volatile("{ .reg .u64 g; cvta.to.global.u64 g, %1; "
                 "cp.async.cg.shared.global [%0], [g], 16; }"
                 :: "r"(dst), "l"(src));
}
DI void cpa_commit() { asm volatile("cp.async.commit_group;" ::: "memory"); }
DI void cpa_wait0() { asm volatile("cp.async.wait_group 0;" ::: "memory"); }
DI void cpa_wait1() { asm volatile("cp.async.wait_group 1;" ::: "memory"); }

DI void ldsm4(uint32_t (&r)[4], uint32_t addr) {
    asm volatile("ldmatrix.sync.aligned.m8n8.x4.shared.b16 {%0,%1,%2,%3}, [%4];"
                 : "=r"(r[0]), "=r"(r[1]), "=r"(r[2]), "=r"(r[3]) : "r"(addr));
}

DI void mma16816(float (&d)[4], const uint32_t (&a)[4], uint32_t b0, uint32_t b1) {
    asm volatile("mma.sync.aligned.m16n8k16.row.col.f32.bf16.bf16.f32 "
                 "{%0,%1,%2,%3}, {%4,%5,%6,%7}, {%8,%9}, {%0,%1,%2,%3};"
                 : "+f"(d[0]), "+f"(d[1]), "+f"(d[2]), "+f"(d[3])
                 : "r"(a[0]), "r"(a[1]), "r"(a[2]), "r"(a[3]), "r"(b0), "r"(b1));
}

// XOR-swizzled tile: row stride 256 B (128 bf16), 16B chunk c -> c ^ (row&7)
DI uint32_t tile_off(int r, int chunk) { return (uint32_t)(r * 256 + ((chunk ^ (r & 7)) << 4)); }

DI uint32_t pk(float a, float b) {
    __nv_bfloat16 ha = __float2bfloat16(a), hb = __float2bfloat16(b);
    return ((uint32_t)__bfloat16_as_ushort(hb) << 16) | (uint32_t)__bfloat16_as_ushort(ha);
}
DI uint32_t pksplit(float a, float b, float& ra, float& rb) {
    __nv_bfloat16 ha = __float2bfloat16(a), hb = __float2bfloat16(b);
    ra = a - __bfloat162float(ha);
    rb = b - __bfloat162float(hb);
    return ((uint32_t)__bfloat16_as_ushort(hb) << 16) | (uint32_t)__bfloat16_as_ushort(ha);
}

// Async-load one 32-token A chunk (hi at dst, lo at dst+8192), swizzled.
DI void load_chunkA(uint32_t dst, const __nv_bfloat16* __restrict__ Ah,
                    const __nv_bfloat16* __restrict__ Al, size_t m0, int t)
{
    const uint4* sh_ = (const uint4*)(Ah + m0 * 128);
    const uint4* sl_ = (const uint4*)(Al + m0 * 128);
    for (int i = t; i < 512; i += 256) {
        int r = i >> 4, c = i & 15;
        uint32_t o = tile_off(r, c);
        cpa16(dst + o, sh_ + i);
        cpa16(dst + 8192 + o, sl_ + i);
    }
}

// ---------------------------------------------------------------------------
// Weight prep: fold BN, transpose to [n][k], split bf16 hi/lo
// ---------------------------------------------------------------------------
__global__ void prep_weights(const float* __restrict__ w_pw0, const float* __restrict__ w_pw1,
                             const float* __restrict__ w_vp,  const float* __restrict__ w_om,
                             const float* __restrict__ w_op,
                             const float* __restrict__ bn1_g, const float* __restrict__ bn1_v,
                             const float* __restrict__ bn2_g, const float* __restrict__ bn2_v)
{
    int idx = blockIdx.x * blockDim.x + threadIdx.x;
    if (idx >= 73728) return;
    float w; __nv_bfloat16 *H, *L; int off;
    if (idx < 16384) {
        int k = idx & 127;
        w = w_pw0[idx] * bn1_g[k] * rsqrtf(bn1_v[k] + EPS);
        H = g_w1h; L = g_w1l; off = idx;
    } else if (idx < 32768) {
        int j = idx - 16384; int k = j & 127;
        w = w_pw1[j] * bn2_g[k] * rsqrtf(bn2_v[k] + EPS);
        H = g_w5h; L = g_w5l; off = j;
    } else if (idx < 49152) {
        int j = idx - 32768; int n = j >> 7, k = j & 127;
        w = w_op[k * 128 + n];
        H = g_w4h; L = g_w4l; off = j;
    } else {
        int j = idx - 49152; int n = j >> 7, k = j & 127;
        w = (n < 128) ? w_vp[k * 128 + n] : ((n < 155) ? w_om[k * 32 + (n - 128)] : 0.f);
        H = g_w2h; L = g_w2l; off = j;
    }
    __nv_bfloat16 h = __float2bfloat16(w);
    H[off] = h;
    L[off] = __float2bfloat16(w - __bfloat162float(h));
}

__global__ void prep_bias(const float* __restrict__ bn1_g, const float* __restrict__ bn1_b,
                          const float* __restrict__ bn1_m, const float* __restrict__ bn1_v,
                          const float* __restrict__ bn2_g, const float* __restrict__ bn2_b,
                          const float* __restrict__ bn2_m, const float* __restrict__ bn2_v,
                          const float* __restrict__ w_pw0, const float* __restrict__ w_pw1,
                          const float* __restrict__ b_vp,  const float* __restrict__ b_om)
{
    int t = threadIdx.x;
    if (t < 128) {
        float s = 0.f;
        for (int c = 0; c < 128; ++c) {
            float sc = bn1_g[c] * rsqrtf(bn1_v[c] + EPS);
            s += w_pw0[t * 128 + c] * (bn1_b[c] - bn1_m[c] * sc);
        }
        g_bias0[t] = s;
        float s2 = 0.f;
        for (int c = 0; c < 128; ++c) {
            float sc = bn2_g[c] * rsqrtf(bn2_v[c] + EPS);
            s2 += w_pw1[t * 128 + c] * (bn2_b[c] - bn2_m[c] * sc);
        }
        g_bias1[t] = s2;
    }
    if (t < 192) {
        g_bcat[t] = (t < 128) ? b_vp[t] : ((t < 155) ? b_om[t - 128] : 0.f);
        g_zero[t] = 0.f;
    }
}

// ---------------------------------------------------------------------------
// Transpose-convert: per batch view [128 k][4096 s] -> token-major bf16 hi/lo
// ---------------------------------------------------------------------------
__global__ void __launch_bounds__(256, 4)
tconv(const float* __restrict__ in, __nv_bfloat16* __restrict__ oh, __nv_bfloat16* __restrict__ ol)
{
    __shared__ float tile[32][129];
    int b = blockIdx.z, k0 = blockIdx.y * 32, s0 = blockIdx.x * 128;
    const float* src = in + (size_t)b * 524288 + (size_t)k0 * 4096 + s0;
    for (int i = threadIdx.x; i < 1024; i += 256) {
        int kk = i >> 5, s4 = (i & 31) << 2;
        float4 v = *(const float4*)(src + (size_t)kk * 4096 + s4);
        tile[kk][s4] = v.x; tile[kk][s4 + 1] = v.y; tile[kk][s4 + 2] = v.z; tile[kk][s4 + 3] = v.w;
    }
    __syncthreads();
    for (int i = threadIdx.x; i < 1024; i += 256) {
        int s = i >> 3, q = i & 7, k = q << 2;
        float v0 = tile[k][s], v1 = tile[k + 1][s], v2 = tile[k + 2][s], v3 = tile[k + 3][s];
        uint2 hq, lq; float l0, l1, l2, l3;
        hq.x = pksplit(v0, v1, l0, l1); hq.y = pksplit(v2, v3, l2, l3);
        lq.x = pk(l0, l1);              lq.y = pk(l2, l3);
        size_t row = (size_t)b * 4096 + s0 + s;
        ((uint2*)(oh + row * 128 + k0))[q] = hq;
        ((uint2*)(ol + row * 128 + k0))[q] = lq;
    }
}

// ---------------------------------------------------------------------------
// Persistent chunk-loop HMMA GEMM. bf16x3 split (AhBh+AhBl+AlBh), fp32 acc.
// 32-token chunks; 8 warps = 2(m,16) x 4(n,N/4). Split-passes reordered so
// same-accumulator MMAs are separated by 2*NP independent MMAs.
// MODE 0: fp32 row-major direct register stores (ldo)
// MODE 1: bf16 hi/lo raw-reshape scatter into step-2 A layout (smem stage)
// MODE 2: fp32 NCHW final output (smem stage)
// ---------------------------------------------------------------------------
template<int N, int MODE, int MINB>
__global__ void __launch_bounds__(256, MINB)
gemm_mma(const __nv_bfloat16* __restrict__ Ah, const __nv_bfloat16* __restrict__ Al,
         const __nv_bfloat16* __restrict__ Bh, const __nv_bfloat16* __restrict__ Bl,
         const float* __restrict__ biasj,
         float* __restrict__ outF, int ldo,
         __nv_bfloat16* __restrict__ outH, __nv_bfloat16* __restrict__ outL)
{
    constexpr int NW = N / 4;        // per-warp n width
    constexpr int NT = NW / 8;       // 8-col n-tiles per warp
    constexpr int NP = NW / 16;      // ldmatrix n-pairs per warp
    constexpr int BOFF = 2 * N * 256;
    constexpr int ldp = N + 1;

    extern __shared__ char sm[];
    const uint32_t uSM = smem_u32(sm);
    const uint32_t uBh = uSM, uBl = uSM + N * 256;
    float* stage = (float*)(sm + BOFF + 32768);

    const int t = threadIdx.x, w = t >> 5, l = t & 31;
    const int wm = w & 1, wn = w >> 1;
    const int nb0 = wn * NW;

    // hoist bias
    const int cbase = (l & 3) * 2;
    float bj0[NT], bj1[NT];
#pragma unroll
    for (int nt = 0; nt < NT; nt++) {
        int col = nb0 + nt * 8 + cbase;
        bj0[nt] = biasj[col];
        bj1[nt] = biasj[col + 1];
    }

    // B load (once)
    {
        const uint4* sh_ = (const uint4*)Bh;
        const uint4* sl_ = (const uint4*)Bl;
        for (int i = t; i < N * 16; i += 256) {
            int r = i >> 4, c = i & 15;
            uint32_t o = tile_off(r, c);
            cpa16(uBh + o, sh_ + i);
            cpa16(uBl + o, sl_ + i);
        }
    }
    int cid = blockIdx.x;
    load_chunkA(uSM + BOFF, Ah, Al, (size_t)cid * CH, t);
    cpa_commit();

    const int arow0 = wm * 16 + (l & 15);
    const int akhalf = l >> 4;
    const int brow_off = (l & 7) + ((l & 16) >> 1);
    const int bkhalf = (l >> 3) & 1;

    int p = 0;
    while (cid < CHUNKS) {
        const int nxt = cid + (int)gridDim.x;
        const bool hasnext = nxt < CHUNKS;
        if (hasnext) {
            load_chunkA(uSM + BOFF + (p ^ 1) * 16384, Ah, Al, (size_t)nxt * CH, t);
            cpa_commit();
            cpa_wait1();
        } else {
            cpa_wait0();
        }
        __syncthreads();

        const uint32_t uAh = uSM + BOFF + p * 16384;
        const uint32_t uAl = uAh + 8192;

        float d[NT][4];
#pragma unroll
        for (int nt = 0; nt < NT; nt++)
#pragma unroll
            for (int i = 0; i < 4; i++) d[nt][i] = 0.f;

#pragma unroll
        for (int ks = 0; ks < 8; ks++) {
            uint32_t ah[4], al[4];
            {
                uint32_t off = tile_off(arow0, 2 * ks + akhalf);
                ldsm4(ah, uAh + off);
                ldsm4(al, uAl + off);
            }
            uint32_t bh[NP][4], bl[NP][4];
#pragma unroll
            for (int np = 0; np < NP; np++) {
                uint32_t off = tile_off(nb0 + np * 16 + brow_off, 2 * ks + bkhalf);
                ldsm4(bh[np], uBh + off);
                ldsm4(bl[np], uBl + off);
            }
            // pass 1: Ah*Bh
#pragma unroll
            for (int np = 0; np < NP; np++) {
                mma16816(d[2 * np],     ah, bh[np][0], bh[np][1]);
                mma16816(d[2 * np + 1], ah, bh[np][2], bh[np][3]);
            }
            // pass 2: Ah*Bl
#pragma unroll
            for (int np = 0; np < NP; np++) {
                mma16816(d[2 * np],     ah, bl[np][0], bl[np][1]);
                mma16816(d[2 * np + 1], ah, bl[np][2], bl[np][3]);
            }
            // pass 3: Al*Bh
#pragma unroll
            for (int np = 0; np < NP; np++) {
                mma16816(d[2 * np],     al, bh[np][0], bh[np][1]);
                mma16816(d[2 * np + 1], al, bh[np][2], bh[np][3]);
            }
        }

        const size_t m0 = (size_t)cid * CH;
        const int rbase = wm * 16 + (l >> 2);

        if (MODE == 0) {
#pragma unroll
            for (int nt = 0; nt < NT; nt++) {
                int col = nb0 + nt * 8 + cbase;
                float2 v0 = make_float2(d[nt][0] + bj0[nt], d[nt][1] + bj1[nt]);
                float2 v1 = make_float2(d[nt][2] + bj0[nt], d[nt][3] + bj1[nt]);
                *(float2*)(outF + (m0 + rbase) * (size_t)ldo + col) = v0;
                *(float2*)(outF + (m0 + rbase + 8) * (size_t)ldo + col) = v1;
            }
        } else {
#pragma unroll
            for (int nt = 0; nt < NT; nt++) {
                int col = nb0 + nt * 8 + cbase;
                stage[rbase * ldp + col]           = d[nt][0] + bj0[nt];
                stage[rbase * ldp + col + 1]       = d[nt][1] + bj1[nt];
                stage[(rbase + 8) * ldp + col]     = d[nt][2] + bj0[nt];
                stage[(rbase + 8) * ldp + col + 1] = d[nt][3] + bj1[nt];
            }
            __syncthreads();
            if (MODE == 1) {
                // scatter: D[(b,s)][n] -> A2[b*4096 + n*32 + s>>7][s&127]
                const int b  = (int)(m0 >> 12);
                const int sh = (int)((m0 & 4095) >> 7);
                const int cb = (int)(m0 & 96);
                for (int i = t; i < N * 8; i += 256) {
                    int n = i >> 3, q = i & 7, j0 = q * 4;
                    float v0 = stage[(j0 + 0) * ldp + n], v1 = stage[(j0 + 1) * ldp + n];
                    float v2 = stage[(j0 + 2) * ldp + n], v3 = stage[(j0 + 3) * ldp + n];
                    uint2 hq, lq; float r0, r1, r2, r3;
                    hq.x = pksplit(v0, v1, r0, r1); hq.y = pksplit(v2, v3, r2, r3);
                    lq.x = pk(r0, r1);              lq.y = pk(r2, r3);
                    size_t row = (size_t)b * 4096 + (size_t)n * 32 + sh;
                    ((uint2*)(outH + row * 128 + cb))[q] = hq;
                    ((uint2*)(outL + row * 128 + cb))[q] = lq;
                }
            } else {
                // NCHW: D[(b, s0+j)][n] -> out[b][n][s0+j]
                const int b  = (int)(m0 >> 12);
                const int s0 = (int)(m0 & 4095);
                for (int i = t; i < N * 8; i += 256) {
                    int n = i >> 3, q = i & 7, j0 = q * 4;
                    float4 v = make_float4(stage[(j0 + 0) * ldp + n], stage[(j0 + 1) * ldp + n],
                                           stage[(j0 + 2) * ldp + n], stage[(j0 + 3) * ldp + n]);
                    *(float4*)(outF + (size_t)b * 524288 + (size_t)n * 4096 + s0 + j0) = v;
                }
            }
        }
        __syncthreads();   // protect A buffer / stage before next iteration
        p ^= 1;
        cid = nxt;
    }
}

// ---------------------------------------------------------------------------
// DCNv4 core (fp32) -> bf16 hi/lo output
// ---------------------------------------------------------------------------
__global__ void dcn_kernel(const float* __restrict__ vpom,
                           __nv_bfloat16* __restrict__ oh, __nv_bfloat16* __restrict__ ol)
{
    const int warp = threadIdx.x >> 5;
    const int lane = threadIdx.x & 31;
    const int pos  = blockIdx.x * 8 + warp;
    const int b = pos >> 12;
    const int s = pos & 4095;
    const int h = s >> 6;
    const int w = s & 63;

    const float* omp = vpom + (size_t)pos * 192 + 128;
    float omv = (lane < 27) ? omp[lane] : 0.f;

    const float* vb = vpom + ((size_t)b << 12) * 192;
    const int coff = lane << 2;

    float4 acc = make_float4(0.f, 0.f, 0.f, 0.f);

#pragma unroll
    for (int k = 0; k < 9; ++k) {
        float dx = __shfl_sync(0xffffffffu, omv, 3 * k);
        float dy = __shfl_sync(0xffffffffu, omv, 3 * k + 1);
        float m  = __shfl_sync(0xffffffffu, omv, 3 * k + 2);
        float px = (float)(w + (k % 3) - 1) + dx;
        float py = (float)(h + (k / 3) - 1) + dy;
        float xf = floorf(px), yf = floorf(py);
        float fx = px - xf,    fy = py - yf;
        int x0 = (int)xf, y0 = (int)yf;
#pragma unroll
        for (int cy = 0; cy < 2; ++cy) {
#pragma unroll
            for (int cx = 0; cx < 2; ++cx) {
                int xi = x0 + cx, yi = y0 + cy;
                float wt = (cx ? fx : 1.f - fx) * (cy ? fy : 1.f - fy) * m;
                if (xi < 0 || xi > 63 || yi < 0 || yi > 63) wt = 0.f;
                int xc = min(max(xi, 0), 63);
                int yc = min(max(yi, 0), 63);
                const float4 v = *(const float4*)(vb + (size_t)(yc * 64 + xc) * 192 + coff);
                acc.x += wt * v.x; acc.y += wt * v.y;
                acc.z += wt * v.z; acc.w += wt * v.w;
            }
        }
    }
    uint2 hq, lq; float l0, l1, l2, l3;
    hq.x = pksplit(acc.x, acc.y, l0, l1); hq.y = pksplit(acc.z, acc.w, l2, l3);
    lq.x = pk(l0, l1);                    lq.y = pk(l2, l3);
    *(uint2*)(oh + (size_t)pos * 128 + coff) = hq;
    *(uint2*)(ol + (size_t)pos * 128 + coff) = lq;
}

// ---------------------------------------------------------------------------
// Launcher
// ---------------------------------------------------------------------------
extern "C" void kernel_launch(void* const* d_in, const int* in_sizes, int n_in,
                              void* d_out, int out_size)
{
    (void)in_sizes; (void)n_in; (void)out_size;
    const float* x     = (const float*)d_in[0];
    const float* bn1_g = (const float*)d_in[1];
    const float* bn1_b = (const float*)d_in[2];
    const float* bn1_m = (const float*)d_in[3];
    const float* bn1_v = (const float*)d_in[4];
    const float* w_pw0 = (const float*)d_in[5];
    const float* w_vp  = (const float*)d_in[6];
    const float* b_vp  = (const float*)d_in[7];
    const float* w_om  = (const float*)d_in[8];
    const float* b_om  = (const float*)d_in[9];
    const float* w_op  = (const float*)d_in[10];
    const float* bn2_g = (const float*)d_in[11];
    const float* bn2_b = (const float*)d_in[12];
    const float* bn2_m = (const float*)d_in[13];
    const float* bn2_v = (const float*)d_in[14];
    const float* w_pw1 = (const float*)d_in[15];
    float* out = (float*)d_out;

    __nv_bfloat16 *xth, *xtl, *a2h, *a2l, *dch, *dcl, *oth, *otl;
    __nv_bfloat16 *w1h, *w1l, *w2h, *w2l, *w4h, *w4l, *w5h, *w5l;
    float *vpom, *op, *bias0, *bias1, *bcat, *zero;
    cudaGetSymbolAddress((void**)&xth, g_xt_hi);  cudaGetSymbolAddress((void**)&xtl, g_xt_lo);
    cudaGetSymbolAddress((void**)&a2h, g_a2_hi);  cudaGetSymbolAddress((void**)&a2l, g_a2_lo);
    cudaGetSymbolAddress((void**)&dch, g_dcn_hi); cudaGetSymbolAddress((void**)&dcl, g_dcn_lo);
    cudaGetSymbolAddress((void**)&oth, g_ot_hi);  cudaGetSymbolAddress((void**)&otl, g_ot_lo);
    cudaGetSymbolAddress((void**)&w1h, g_w1h);    cudaGetSymbolAddress((void**)&w1l, g_w1l);
    cudaGetSymbolAddress((void**)&w2h, g_w2h);    cudaGetSymbolAddress((void**)&w2l, g_w2l);
    cudaGetSymbolAddress((void**)&w4h, g_w4h);    cudaGetSymbolAddress((void**)&w4l, g_w4l);
    cudaGetSymbolAddress((void**)&w5h, g_w5h);    cudaGetSymbolAddress((void**)&w5l, g_w5l);
    cudaGetSymbolAddress((void**)&vpom, g_vpom);  cudaGetSymbolAddress((void**)&op, g_op);
    cudaGetSymbolAddress((void**)&bias0, g_bias0); cudaGetSymbolAddress((void**)&bias1, g_bias1);
    cudaGetSymbolAddress((void**)&bcat, g_bcat);  cudaGetSymbolAddress((void**)&zero, g_zero);

    // smem: B(2*N*256) + A dbuf(2*16KB... 32768 for CH=32) + stage(32*(N+1)*4)
    const int SM128 = 2 * 128 * 256 + 32768 + 32 * 129 * 4;   // 114816 -> 2 CTAs/SM
    const int SM192 = 2 * 192 * 256 + 32768 + 32 * 193 * 4;   // 155776 -> 1 CTA/SM
    cudaFuncSetAttribute((const void*)gemm_mma<128, 0, 2>, cudaFuncAttributeMaxDynamicSharedMemorySize, SM128);
    cudaFuncSetAttribute((const void*)gemm_mma<128, 1, 2>, cudaFuncAttributeMaxDynamicSharedMemorySize, SM128);
    cudaFuncSetAttribute((const void*)gemm_mma<128, 2, 2>, cudaFuncAttributeMaxDynamicSharedMemorySize, SM128);
    cudaFuncSetAttribute((const void*)gemm_mma<192, 0, 1>, cudaFuncAttributeMaxDynamicSharedMemorySize, SM192);

    const int G128 = 296;   // 2 persistent CTAs per SM
    const int G192 = 148;   // 1 persistent CTA per SM

    prep_weights<<<288, 256>>>(w_pw0, w_pw1, w_vp, w_om, w_op, bn1_g, bn1_v, bn2_g, bn2_v);
    prep_bias<<<1, 256>>>(bn1_g, bn1_b, bn1_m, bn1_v, bn2_g, bn2_b, bn2_m, bn2_v,
                          w_pw0, w_pw1, b_vp, b_om);

    // 1) x (NCHW) -> token-major hi/lo; x1 = x @ w1^T + bias0 scattered into
    //    step-2's raw-reshape A layout.
    tconv<<<dim3(32, 4, 8), 256>>>(x, xth, xtl);
    gemm_mma<128, 1, 2><<<G128, 256, SM128>>>(xth, xtl, w1h, w1l, bias0, nullptr, 0, a2h, a2l);

    // 2) vpom = x1_view @ [w_vp|w_om]^T + bcat  (fp32, ld 192)
    gemm_mma<192, 0, 1><<<G192, 256, SM192>>>(a2h, a2l, w2h, w2l, bcat, vpom, 192, nullptr, nullptr);

    // 3) DCNv4 core -> bf16 hi/lo
    dcn_kernel<<<4096, 256>>>(vpom, dch, dcl);

    // 4) op = dcn @ w_op  (fp32 token-major = NCHW raw view)
    gemm_mma<128, 0, 2><<<G128, 256, SM128>>>(dch, dcl, w4h, w4l, zero, op, 128, nullptr, nullptr);

    // 5) out = (BN2-folded pw1) on NCHW view of op
    tconv<<<dim3(32, 4, 8), 256>>>(op, oth, otl);
    gemm_mma<128, 2, 2><<<G128, 256, SM128>>>(oth, otl, w5h, w5l, bias1, out, 0, nullptr, nullptr);
}